// round 16
// baseline (speedup 1.0000x reference)
#include <cuda_runtime.h>
#include <cstdint>

// out[0, z, r, c, ch] = in[0, z_idx[z], row_idx[r], col_idx[c], 0]
// in (1,128,128,128,32) f32; idx arrays 64 x int32; out (1,64,64,64,32) f32.
//
// Two-phase split so DRAM sees (almost) pure traffic per kernel:
//   Phase 1: scattered gather (8 MB of 32B sectors) -> compact 1 MB scratch.
//   Phase 2: scratch (L2-resident from phase 1) -> 32 MB streamed STG.256.

__device__ float g_scratch[64 * 64 * 64];   // 1 MB, compact g[v]

__global__ __launch_bounds__(256) void gather_kernel(
    const float* __restrict__ in,
    const int*   __restrict__ z_idx,
    const int*   __restrict__ row_idx,
    const int*   __restrict__ col_idx)
{
    unsigned v = blockIdx.x * blockDim.x + threadIdx.x;   // 0 .. 262143
    unsigned c = v & 63;
    unsigned r = (v >> 6) & 63;
    unsigned z = v >> 12;

    unsigned zz = (unsigned)__ldg(z_idx + z);     // warp-uniform
    unsigned rr = (unsigned)__ldg(row_idx + r);   // warp-uniform (2 rows/warp)
    unsigned cc = (unsigned)__ldg(col_idx + c);

    const float* src = in + (((zz << 7 | rr) << 7 | cc) << 5);
    float val;
    asm volatile("ld.global.cs.f32 %0, [%1];" : "=f"(val) : "l"(src));

    g_scratch[v] = val;   // coalesced, lands in L2 for phase 2
}

#define N_V8  (8388608 / 8)   // 1,048,576 v8 stores

__global__ __launch_bounds__(256) void broadcast_kernel(
    float* __restrict__ out)
{
    unsigned g = blockIdx.x * blockDim.x + threadIdx.x;  // 0 .. 2^20-1
    unsigned v = g >> 2;                                 // 4 lanes per voxel

    float val = __ldg(&g_scratch[v]);   // L2 hit (1 MB working set)

    float* p = out + (size_t)g * 8;     // 32B-aligned
    asm volatile(
        "st.global.v8.f32 [%0], {%1,%1,%1,%1,%1,%1,%1,%1};"
        :: "l"(p), "f"(val) : "memory");
}

extern "C" void kernel_launch(void* const* d_in, const int* in_sizes, int n_in,
                              void* d_out, int out_size)
{
    const float* in      = (const float*)d_in[0];
    const int*   z_idx   = (const int*)d_in[1];
    const int*   row_idx = (const int*)d_in[2];
    const int*   col_idx = (const int*)d_in[3];
    float* out = (float*)d_out;

    gather_kernel<<<262144 / 256, 256>>>(in, z_idx, row_idx, col_idx);
    broadcast_kernel<<<N_V8 / 256, 256>>>(out);
}